// round 2
// baseline (speedup 1.0000x reference)
#include <cuda_runtime.h>
#include <math.h>

// Problem constants
#define B_  2
#define S_  2048
#define D_  1024
#define H_  16
#define C_  64
#define M_  (B_ * S_)      // 4096 rows for all projection GEMMs
#define N_  (H_ * C_)      // 1024 cols

// q scaled by C^-0.5 * log2(e) so softmax can run in base-2 (exp2 via FMA poly)
#define QSCALE 0.18033688011112042f

// Scratch (device globals: allocation-free rule)
__device__ float g_q[M_ * N_];
__device__ float g_k[M_ * N_];
__device__ float g_v[M_ * N_];
__device__ float g_o[M_ * N_];

// ---------------------------------------------------------------------------
// Fast exp2 on the FMA pipe (avoids MUFU bottleneck).
// Valid for x <= 0 (softmax inputs are s - max <= 0). Max rel err ~1.5e-7.
// ---------------------------------------------------------------------------
__device__ __forceinline__ float fexp2(float x) {
    x = fmaxf(x, -110.0f);
    float r = rintf(x);
    float f = x - r;                      // f in [-0.5, 0.5]
    float p =            1.5403530e-4f;   // ln2^6/720
    p = fmaf(p, f,       1.3333558e-3f);  // ln2^5/120
    p = fmaf(p, f,       9.6181291e-3f);  // ln2^4/24
    p = fmaf(p, f,       5.5504109e-2f);  // ln2^3/6
    p = fmaf(p, f,       2.4022651e-1f);  // ln2^2/2
    p = fmaf(p, f,       6.9314718e-1f);  // ln2
    p = fmaf(p, f,       1.0f);
    int e = (int)r;
    return __int_as_float(__float_as_int(p) + (e << 23));
}

// ---------------------------------------------------------------------------
// SGEMM: C[4096,1024] = alpha * A[4096,1024] @ B[1024,1024]
// 128x128 block tile, BK=16, 256 threads, 8x8 microtile.
// ---------------------------------------------------------------------------
__global__ __launch_bounds__(256)
void sgemm_kernel(const float* __restrict__ A, const float* __restrict__ Bm,
                  float* __restrict__ Cm, float alpha) {
    const int K = 1024, N = 1024;
    __shared__ float As[16][128];   // transposed A tile: As[k][m]
    __shared__ float Bs[16][128];   // Bs[k][n]

    int tid = threadIdx.x;
    int tx = tid & 15;              // 0..15 -> output col group
    int ty = tid >> 4;              // 0..15 -> output row group
    int bm = blockIdx.y * 128;
    int bn = blockIdx.x * 128;

    // load mapping
    int arow = tid >> 2;            // 0..63
    int akc  = (tid & 3) << 2;      // 0,4,8,12
    int brow = tid >> 5;            // 0..7
    int bcol = (tid & 31) << 2;     // 0..124

    const float* Ab = A + (size_t)bm * K;
    const float* Bb = Bm + bn;

    float acc[8][8];
#pragma unroll
    for (int i = 0; i < 8; i++)
#pragma unroll
        for (int j = 0; j < 8; j++) acc[i][j] = 0.0f;

    for (int k0 = 0; k0 < K; k0 += 16) {
        float4 a0 = *(const float4*)(Ab + (size_t)arow * K + k0 + akc);
        float4 a1 = *(const float4*)(Ab + (size_t)(arow + 64) * K + k0 + akc);
        float4 b0 = *(const float4*)(Bb + (size_t)(k0 + brow) * N + bcol);
        float4 b1 = *(const float4*)(Bb + (size_t)(k0 + brow + 8) * N + bcol);

        __syncthreads();   // protect smem from previous iteration's readers
        As[akc + 0][arow] = a0.x;  As[akc + 1][arow] = a0.y;
        As[akc + 2][arow] = a0.z;  As[akc + 3][arow] = a0.w;
        As[akc + 0][arow + 64] = a1.x;  As[akc + 1][arow + 64] = a1.y;
        As[akc + 2][arow + 64] = a1.z;  As[akc + 3][arow + 64] = a1.w;
        *(float4*)(&Bs[brow][bcol])     = b0;
        *(float4*)(&Bs[brow + 8][bcol]) = b1;
        __syncthreads();

#pragma unroll
        for (int kk = 0; kk < 16; kk++) {
            float4 ra0 = *(float4*)(&As[kk][ty * 8]);
            float4 ra1 = *(float4*)(&As[kk][ty * 8 + 4]);
            float4 rb0 = *(float4*)(&Bs[kk][tx * 8]);
            float4 rb1 = *(float4*)(&Bs[kk][tx * 8 + 4]);
            float ra[8] = {ra0.x, ra0.y, ra0.z, ra0.w, ra1.x, ra1.y, ra1.z, ra1.w};
            float rb[8] = {rb0.x, rb0.y, rb0.z, rb0.w, rb1.x, rb1.y, rb1.z, rb1.w};
#pragma unroll
            for (int i = 0; i < 8; i++)
#pragma unroll
                for (int j = 0; j < 8; j++)
                    acc[i][j] = fmaf(ra[i], rb[j], acc[i][j]);
        }
    }

#pragma unroll
    for (int i = 0; i < 8; i++) {
        float* Crow = Cm + (size_t)(bm + ty * 8 + i) * N + bn + tx * 8;
        float4 c0 = make_float4(alpha * acc[i][0], alpha * acc[i][1],
                                alpha * acc[i][2], alpha * acc[i][3]);
        float4 c1 = make_float4(alpha * acc[i][4], alpha * acc[i][5],
                                alpha * acc[i][6], alpha * acc[i][7]);
        *(float4*)Crow       = c0;
        *(float4*)(Crow + 4) = c1;
    }
}

// ---------------------------------------------------------------------------
// Flash attention: one block = (b, h, 128-query tile). 64-key tiles.
// q/k/v layout: [B*S, H*C] row-major (col = h*64 + c). Scores already carry
// the log2(e)/sqrt(C) factor via QSCALE, so softmax uses exp2.
// Thread microtile: 8 query rows (ty) x 4 key cols (tx). Threads sharing a
// query row are the 16 lanes of one half-warp -> shfl_xor width-16 reductions.
// ---------------------------------------------------------------------------
#define QS_STRIDE 132   // 128 + 4 pad (float4-aligned, bank-skewed)
#define KS_STRIDE 65    // 64 + 1 pad (conflict-light column reads)
#define PS_STRIDE 65

#define SM_QS 0
#define SM_KS (SM_QS + 64 * QS_STRIDE)                 // 8448
#define SM_VS (SM_KS + 64 * KS_STRIDE)                 // 12608
#define SM_PS (SM_VS + 64 * 64)                        // 16704
#define SM_FLOATS (SM_PS + 128 * PS_STRIDE)            // 25024
#define ATTN_SMEM_BYTES (SM_FLOATS * 4)                // 100096 B

__global__ __launch_bounds__(256, 2)
void attn_kernel(const float* __restrict__ Q, const float* __restrict__ K,
                 const float* __restrict__ V, float* __restrict__ O) {
    extern __shared__ float sm[];
    float* Qs = sm + SM_QS;   // [64][132] transposed: Qs[c][m]
    float* Ks = sm + SM_KS;   // [64][65]  row-major:  Ks[n][c]
    float* Vs = sm + SM_VS;   // [64][64]  row-major:  Vs[n][c]
    float* Ps = sm + SM_PS;   // [128][65]

    int qt = blockIdx.x;      // 0..15
    int h  = blockIdx.y;      // 0..15
    int b  = blockIdx.z;      // 0..1
    int tid = threadIdx.x;
    int tx = tid & 15;
    int ty = tid >> 4;

    const float* Qg = Q + (size_t)(b * S_ + qt * 128) * N_ + h * C_;
    const float* Kg = K + (size_t)(b * S_) * N_ + h * C_;
    const float* Vg = V + (size_t)(b * S_) * N_ + h * C_;

    // Load Q tile (once), transposed into Qs[c][m]
    for (int i = tid; i < 128 * 16; i += 256) {
        int row = i >> 4;
        int c4  = (i & 15) << 2;
        float4 q = *(const float4*)(Qg + (size_t)row * N_ + c4);
        Qs[(c4 + 0) * QS_STRIDE + row] = q.x;
        Qs[(c4 + 1) * QS_STRIDE + row] = q.y;
        Qs[(c4 + 2) * QS_STRIDE + row] = q.z;
        Qs[(c4 + 3) * QS_STRIDE + row] = q.w;
    }

    float o[8][4];
    float mrow[8], lrow[8];
#pragma unroll
    for (int i = 0; i < 8; i++) {
        mrow[i] = -1e30f;
        lrow[i] = 0.0f;
#pragma unroll
        for (int u = 0; u < 4; u++) o[i][u] = 0.0f;
    }

    for (int kt = 0; kt < S_ / 64; kt++) {
        __syncthreads();   // previous iteration done with Ks/Vs/Ps; Qs ready
        // Load K,V tiles (64 keys x 64 channels)
        const float* Kt = Kg + (size_t)kt * 64 * N_;
        const float* Vt = Vg + (size_t)kt * 64 * N_;
        for (int i = tid; i < 64 * 16; i += 256) {
            int row = i >> 4;
            int c4  = (i & 15) << 2;
            float4 kv = *(const float4*)(Kt + (size_t)row * N_ + c4);
            Ks[row * KS_STRIDE + c4 + 0] = kv.x;
            Ks[row * KS_STRIDE + c4 + 1] = kv.y;
            Ks[row * KS_STRIDE + c4 + 2] = kv.z;
            Ks[row * KS_STRIDE + c4 + 3] = kv.w;
            float4 vv = *(const float4*)(Vt + (size_t)row * N_ + c4);
            *(float4*)(Vs + row * 64 + c4) = vv;
        }
        __syncthreads();

        // Phase 1: S = Q K^T for this tile. s[i][j], rows ty*8+i, keys tx*4+j
        float s[8][4];
#pragma unroll
        for (int i = 0; i < 8; i++)
#pragma unroll
            for (int j = 0; j < 4; j++) s[i][j] = 0.0f;

#pragma unroll 8
        for (int c = 0; c < 64; c++) {
            float4 qa = *(float4*)(Qs + c * QS_STRIDE + ty * 8);
            float4 qb = *(float4*)(Qs + c * QS_STRIDE + ty * 8 + 4);
            float qv[8] = {qa.x, qa.y, qa.z, qa.w, qb.x, qb.y, qb.z, qb.w};
            float kr[4];
#pragma unroll
            for (int j = 0; j < 4; j++)
                kr[j] = Ks[(tx * 4 + j) * KS_STRIDE + c];
#pragma unroll
            for (int i = 0; i < 8; i++)
#pragma unroll
                for (int j = 0; j < 4; j++)
                    s[i][j] = fmaf(qv[i], kr[j], s[i][j]);
        }

        // Online softmax (base-2). Width-16 shfl reductions across tx group.
#pragma unroll
        for (int i = 0; i < 8; i++) {
            float mx = fmaxf(fmaxf(s[i][0], s[i][1]), fmaxf(s[i][2], s[i][3]));
            mx = fmaxf(mx, __shfl_xor_sync(0xffffffffu, mx, 8));
            mx = fmaxf(mx, __shfl_xor_sync(0xffffffffu, mx, 4));
            mx = fmaxf(mx, __shfl_xor_sync(0xffffffffu, mx, 2));
            mx = fmaxf(mx, __shfl_xor_sync(0xffffffffu, mx, 1));
            float mnew = fmaxf(mrow[i], mx);
            float corr = fexp2(mrow[i] - mnew);
            float rs = 0.0f;
#pragma unroll
            for (int j = 0; j < 4; j++) {
                float p = fexp2(s[i][j] - mnew);
                s[i][j] = p;
                rs += p;
            }
            rs += __shfl_xor_sync(0xffffffffu, rs, 8);
            rs += __shfl_xor_sync(0xffffffffu, rs, 4);
            rs += __shfl_xor_sync(0xffffffffu, rs, 2);
            rs += __shfl_xor_sync(0xffffffffu, rs, 1);
            lrow[i] = lrow[i] * corr + rs;
            mrow[i] = mnew;
#pragma unroll
            for (int u = 0; u < 4; u++) o[i][u] *= corr;
            // stage P into smem for the P@V GEMM
#pragma unroll
            for (int j = 0; j < 4; j++)
                Ps[(ty * 8 + i) * PS_STRIDE + tx * 4 + j] = s[i][j];
        }
        __syncthreads();

        // Phase 2: O += P @ V.  o[i][u]: rows ty*8+i, channels tx*4+u
#pragma unroll 8
        for (int j = 0; j < 64; j++) {
            float4 vv = *(float4*)(Vs + j * 64 + tx * 4);
#pragma unroll
            for (int i = 0; i < 8; i++) {
                float p = Ps[(ty * 8 + i) * PS_STRIDE + j];
                o[i][0] = fmaf(p, vv.x, o[i][0]);
                o[i][1] = fmaf(p, vv.y, o[i][1]);
                o[i][2] = fmaf(p, vv.z, o[i][2]);
                o[i][3] = fmaf(p, vv.w, o[i][3]);
            }
        }
    }

    // Epilogue: normalize and store O as [B*S, H*C]
#pragma unroll
    for (int i = 0; i < 8; i++) {
        float inv = 1.0f / lrow[i];
        int row = qt * 128 + ty * 8 + i;
        float4 r = make_float4(o[i][0] * inv, o[i][1] * inv,
                               o[i][2] * inv, o[i][3] * inv);
        *(float4*)(O + (size_t)(b * S_ + row) * N_ + h * C_ + tx * 4) = r;
    }
}

// ---------------------------------------------------------------------------
extern "C" void kernel_launch(void* const* d_in, const int* in_sizes, int n_in,
                              void* d_out, int out_size) {
    const float* x  = (const float*)d_in[0];
    const float* Wq = (const float*)d_in[1];
    const float* Wk = (const float*)d_in[2];
    const float* Wv = (const float*)d_in[3];
    const float* Wo = (const float*)d_in[4];
    float* out = (float*)d_out;

    float *q, *k, *v, *o;
    cudaGetSymbolAddress((void**)&q, g_q);
    cudaGetSymbolAddress((void**)&k, g_k);
    cudaGetSymbolAddress((void**)&v, g_v);
    cudaGetSymbolAddress((void**)&o, g_o);

    cudaFuncSetAttribute(attn_kernel,
                         cudaFuncAttributeMaxDynamicSharedMemorySize,
                         ATTN_SMEM_BYTES);

    dim3 gg(N_ / 128, M_ / 128);   // (8, 32)
    dim3 tt(256);

    // QKV projections (q pre-scaled by C^-0.5 * log2(e))
    sgemm_kernel<<<gg, tt>>>(x, Wq, q, QSCALE);
    sgemm_kernel<<<gg, tt>>>(x, Wk, k, 1.0f);
    sgemm_kernel<<<gg, tt>>>(x, Wv, v, 1.0f);

    // Flash attention
    dim3 ga(S_ / 128, H_, B_);     // (16, 16, 2)
    attn_kernel<<<ga, 256, ATTN_SMEM_BYTES>>>(q, k, v, o);

    // Output projection
    sgemm_kernel<<<gg, tt>>>(o, Wo, out, 1.0f);
}

// round 3
// speedup vs baseline: 1.4144x; 1.4144x over previous
#include <cuda_runtime.h>
#include <math.h>

// Problem constants
#define B_  2
#define S_  2048
#define D_  1024
#define H_  16
#define C_  64
#define M_  (B_ * S_)      // 4096 rows for all projection GEMMs
#define N_  (H_ * C_)      // 1024 cols

// q scaled by C^-0.5 * log2(e) so softmax can run in base-2 (exp2 via FMA poly)
#define QSCALE 0.18033688011112042f

// Scratch (device globals: allocation-free rule)
__device__ float g_q[M_ * N_];
__device__ float g_k[M_ * N_];
__device__ float g_v[M_ * N_];
__device__ float g_o[M_ * N_];

typedef unsigned long long u64;

// ---------------------------------------------------------------------------
// Packed f32x2 helpers (Blackwell FFMA2 path — 2x fp32 FMA throughput).
// ---------------------------------------------------------------------------
__device__ __forceinline__ u64 pack2(float lo, float hi) {
    u64 r; asm("mov.b64 %0, {%1, %2};" : "=l"(r) : "f"(lo), "f"(hi)); return r;
}
__device__ __forceinline__ u64 dup2f(float v) { return pack2(v, v); }
__device__ __forceinline__ void unpack2(float& lo, float& hi, u64 v) {
    asm("mov.b64 {%0, %1}, %2;" : "=f"(lo), "=f"(hi) : "l"(v));
}
__device__ __forceinline__ u64 ffma2(u64 a, u64 b, u64 c) {
    u64 d; asm("fma.rn.f32x2 %0, %1, %2, %3;" : "=l"(d) : "l"(a), "l"(b), "l"(c));
    return d;
}
__device__ __forceinline__ u64 fmul2(u64 a, u64 b) {
    u64 d; asm("mul.rn.f32x2 %0, %1, %2;" : "=l"(d) : "l"(a), "l"(b));
    return d;
}

// ---------------------------------------------------------------------------
// Fast exp2 on the FMA pipe (avoids MUFU bottleneck). Max rel err ~1.5e-7.
// ---------------------------------------------------------------------------
__device__ __forceinline__ float fexp2(float x) {
    x = fmaxf(x, -110.0f);
    float r = rintf(x);
    float f = x - r;                      // f in [-0.5, 0.5]
    float p =            1.5403530e-4f;
    p = fmaf(p, f,       1.3333558e-3f);
    p = fmaf(p, f,       9.6181291e-3f);
    p = fmaf(p, f,       5.5504109e-2f);
    p = fmaf(p, f,       2.4022651e-1f);
    p = fmaf(p, f,       6.9314718e-1f);
    p = fmaf(p, f,       1.0f);
    int e = (int)r;
    return __int_as_float(__float_as_int(p) + (e << 23));
}

// ---------------------------------------------------------------------------
// SGEMM: C[4096,1024] = alpha * A[4096,1024] @ B[1024,1024]
// 128x128 block tile, BK=16, 256 threads, 8x8 microtile.
// Microkernel uses FFMA2: accumulators pack adjacent output ROWS (free pairing
// from 64-bit smem loads of As); B values are lane-duplicated once per kk.
// ---------------------------------------------------------------------------
__global__ __launch_bounds__(256)
void sgemm_kernel(const float* __restrict__ A, const float* __restrict__ Bm,
                  float* __restrict__ Cm, float alpha) {
    const int K = 1024, N = 1024;
    __shared__ float As[16][128];   // transposed A tile: As[k][m]
    __shared__ float Bs[16][128];   // Bs[k][n]

    int tid = threadIdx.x;
    int tx = tid & 15;              // output col group
    int ty = tid >> 4;              // output row group
    int bm = blockIdx.y * 128;
    int bn = blockIdx.x * 128;

    int arow = tid >> 2;            // 0..63
    int akc  = (tid & 3) << 2;      // 0,4,8,12
    int brow = tid >> 5;            // 0..7
    int bcol = (tid & 31) << 2;     // 0..124

    const float* Ab = A + (size_t)bm * K;
    const float* Bb = Bm + bn;

    // acc2[i2][j]: packed pair of rows (2*i2, 2*i2+1), col j
    u64 acc2[4][8];
#pragma unroll
    for (int i = 0; i < 4; i++)
#pragma unroll
        for (int j = 0; j < 8; j++) acc2[i][j] = 0ull;

    for (int k0 = 0; k0 < K; k0 += 16) {
        float4 a0 = *(const float4*)(Ab + (size_t)arow * K + k0 + akc);
        float4 a1 = *(const float4*)(Ab + (size_t)(arow + 64) * K + k0 + akc);
        float4 b0 = *(const float4*)(Bb + (size_t)(k0 + brow) * N + bcol);
        float4 b1 = *(const float4*)(Bb + (size_t)(k0 + brow + 8) * N + bcol);

        __syncthreads();
        As[akc + 0][arow] = a0.x;  As[akc + 1][arow] = a0.y;
        As[akc + 2][arow] = a0.z;  As[akc + 3][arow] = a0.w;
        As[akc + 0][arow + 64] = a1.x;  As[akc + 1][arow + 64] = a1.y;
        As[akc + 2][arow + 64] = a1.z;  As[akc + 3][arow + 64] = a1.w;
        *(float4*)(&Bs[brow][bcol])     = b0;
        *(float4*)(&Bs[brow + 8][bcol]) = b1;
        __syncthreads();

#pragma unroll
        for (int kk = 0; kk < 16; kk++) {
            ulonglong2 ap0 = *(ulonglong2*)(&As[kk][ty * 8]);
            ulonglong2 ap1 = *(ulonglong2*)(&As[kk][ty * 8 + 4]);
            u64 a2[4] = {ap0.x, ap0.y, ap1.x, ap1.y};
            float4 rb0 = *(float4*)(&Bs[kk][tx * 8]);
            float4 rb1 = *(float4*)(&Bs[kk][tx * 8 + 4]);
            u64 b2[8] = {dup2f(rb0.x), dup2f(rb0.y), dup2f(rb0.z), dup2f(rb0.w),
                         dup2f(rb1.x), dup2f(rb1.y), dup2f(rb1.z), dup2f(rb1.w)};
#pragma unroll
            for (int i = 0; i < 4; i++)
#pragma unroll
                for (int j = 0; j < 8; j++)
                    acc2[i][j] = ffma2(a2[i], b2[j], acc2[i][j]);
        }
    }

#pragma unroll
    for (int i2 = 0; i2 < 4; i2++) {
        float r0[8], r1[8];
#pragma unroll
        for (int j = 0; j < 8; j++) {
            float lo, hi;
            unpack2(lo, hi, acc2[i2][j]);
            r0[j] = alpha * lo;
            r1[j] = alpha * hi;
        }
        float* C0 = Cm + (size_t)(bm + ty * 8 + 2 * i2)     * N + bn + tx * 8;
        float* C1 = Cm + (size_t)(bm + ty * 8 + 2 * i2 + 1) * N + bn + tx * 8;
        *(float4*)C0       = make_float4(r0[0], r0[1], r0[2], r0[3]);
        *(float4*)(C0 + 4) = make_float4(r0[4], r0[5], r0[6], r0[7]);
        *(float4*)C1       = make_float4(r1[0], r1[1], r1[2], r1[3]);
        *(float4*)(C1 + 4) = make_float4(r1[4], r1[5], r1[6], r1[7]);
    }
}

// ---------------------------------------------------------------------------
// Flash attention: one block = (b, h, 128-query tile). 64-key tiles.
// Phase 1 (QK^T): FFMA2 packs adjacent query rows (free 64-bit Qs loads).
// Phase 2 (P@V):  FFMA2 packs even/odd KEYS into accumulator halves — P loads
//                 become free 64-bit LDS; halves summed once in the epilogue.
// ---------------------------------------------------------------------------
#define QS_STRIDE 132   // 128 + 4 pad
#define KS_STRIDE 65    // 64 + 1 pad
#define PS_STRIDE 66    // 64 + 2 pad (even: keeps u64 loads/stores aligned)

#define SM_QS 0
#define SM_KS (SM_QS + 64 * QS_STRIDE)                 // 8448
#define SM_VS (SM_KS + 64 * KS_STRIDE)                 // 12608
#define SM_PS (SM_VS + 64 * 64)                        // 16704
#define SM_FLOATS (SM_PS + 128 * PS_STRIDE)            // 25152
#define ATTN_SMEM_BYTES (SM_FLOATS * 4)                // 100608 B

__global__ __launch_bounds__(256, 2)
void attn_kernel(const float* __restrict__ Q, const float* __restrict__ K,
                 const float* __restrict__ V, float* __restrict__ O) {
    extern __shared__ float sm[];
    float* Qs = sm + SM_QS;   // [64][132] transposed: Qs[c][m]
    float* Ks = sm + SM_KS;   // [64][65]  row-major:  Ks[n][c]
    float* Vs = sm + SM_VS;   // [64][64]  row-major:  Vs[n][c]
    float* Ps = sm + SM_PS;   // [128][66]

    int qt = blockIdx.x;
    int h  = blockIdx.y;
    int b  = blockIdx.z;
    int tid = threadIdx.x;
    int tx = tid & 15;
    int ty = tid >> 4;

    const float* Qg = Q + (size_t)(b * S_ + qt * 128) * N_ + h * C_;
    const float* Kg = K + (size_t)(b * S_) * N_ + h * C_;
    const float* Vg = V + (size_t)(b * S_) * N_ + h * C_;

    // Load Q tile (once), transposed into Qs[c][m]
    for (int i = tid; i < 128 * 16; i += 256) {
        int row = i >> 4;
        int c4  = (i & 15) << 2;
        float4 q = *(const float4*)(Qg + (size_t)row * N_ + c4);
        Qs[(c4 + 0) * QS_STRIDE + row] = q.x;
        Qs[(c4 + 1) * QS_STRIDE + row] = q.y;
        Qs[(c4 + 2) * QS_STRIDE + row] = q.z;
        Qs[(c4 + 3) * QS_STRIDE + row] = q.w;
    }

    // o2[i][u]: row i, channel u; halves hold even/odd-key partial sums
    u64 o2[8][4];
    float mrow[8], lrow[8];
#pragma unroll
    for (int i = 0; i < 8; i++) {
        mrow[i] = -1e30f;
        lrow[i] = 0.0f;
#pragma unroll
        for (int u = 0; u < 4; u++) o2[i][u] = 0ull;
    }

    for (int kt = 0; kt < S_ / 64; kt++) {
        __syncthreads();
        const float* Kt = Kg + (size_t)kt * 64 * N_;
        const float* Vt = Vg + (size_t)kt * 64 * N_;
        for (int i = tid; i < 64 * 16; i += 256) {
            int row = i >> 4;
            int c4  = (i & 15) << 2;
            float4 kv = *(const float4*)(Kt + (size_t)row * N_ + c4);
            Ks[row * KS_STRIDE + c4 + 0] = kv.x;
            Ks[row * KS_STRIDE + c4 + 1] = kv.y;
            Ks[row * KS_STRIDE + c4 + 2] = kv.z;
            Ks[row * KS_STRIDE + c4 + 3] = kv.w;
            float4 vv = *(const float4*)(Vt + (size_t)row * N_ + c4);
            *(float4*)(Vs + row * 64 + c4) = vv;
        }
        __syncthreads();

        // Phase 1: S = Q K^T. s2[i2][j] packs query rows (2i2, 2i2+1).
        u64 s2[4][4];
#pragma unroll
        for (int i = 0; i < 4; i++)
#pragma unroll
            for (int j = 0; j < 4; j++) s2[i][j] = 0ull;

#pragma unroll 8
        for (int c = 0; c < 64; c++) {
            ulonglong2 qa = *(ulonglong2*)(Qs + c * QS_STRIDE + ty * 8);
            ulonglong2 qb = *(ulonglong2*)(Qs + c * QS_STRIDE + ty * 8 + 4);
            u64 q2[4] = {qa.x, qa.y, qb.x, qb.y};
            u64 k2[4];
#pragma unroll
            for (int j = 0; j < 4; j++)
                k2[j] = dup2f(Ks[(tx * 4 + j) * KS_STRIDE + c]);
#pragma unroll
            for (int i = 0; i < 4; i++)
#pragma unroll
                for (int j = 0; j < 4; j++)
                    s2[i][j] = ffma2(q2[i], k2[j], s2[i][j]);
        }

        // Unpack scores to scalar rows
        float s[8][4];
#pragma unroll
        for (int i2 = 0; i2 < 4; i2++)
#pragma unroll
            for (int j = 0; j < 4; j++)
                unpack2(s[2 * i2][j], s[2 * i2 + 1][j], s2[i2][j]);

        // Online softmax (base-2), width-16 shfl reductions
#pragma unroll
        for (int i = 0; i < 8; i++) {
            float mx = fmaxf(fmaxf(s[i][0], s[i][1]), fmaxf(s[i][2], s[i][3]));
            mx = fmaxf(mx, __shfl_xor_sync(0xffffffffu, mx, 8));
            mx = fmaxf(mx, __shfl_xor_sync(0xffffffffu, mx, 4));
            mx = fmaxf(mx, __shfl_xor_sync(0xffffffffu, mx, 2));
            mx = fmaxf(mx, __shfl_xor_sync(0xffffffffu, mx, 1));
            float mnew = fmaxf(mrow[i], mx);
            float corr = fexp2(mrow[i] - mnew);
            float p0 = fexp2(s[i][0] - mnew);
            float p1 = fexp2(s[i][1] - mnew);
            float p2 = fexp2(s[i][2] - mnew);
            float p3 = fexp2(s[i][3] - mnew);
            float rs = (p0 + p1) + (p2 + p3);
            rs += __shfl_xor_sync(0xffffffffu, rs, 8);
            rs += __shfl_xor_sync(0xffffffffu, rs, 4);
            rs += __shfl_xor_sync(0xffffffffu, rs, 2);
            rs += __shfl_xor_sync(0xffffffffu, rs, 1);
            lrow[i] = lrow[i] * corr + rs;
            mrow[i] = mnew;
            u64 c2 = dup2f(corr);
#pragma unroll
            for (int u = 0; u < 4; u++) o2[i][u] = fmul2(o2[i][u], c2);
            int row = ty * 8 + i;
            *(u64*)(Ps + row * PS_STRIDE + tx * 4)     = pack2(p0, p1);
            *(u64*)(Ps + row * PS_STRIDE + tx * 4 + 2) = pack2(p2, p3);
        }
        __syncthreads();

        // Phase 2: O += P @ V over key pairs (j, j+1) packed in FFMA2 halves
#pragma unroll 4
        for (int j = 0; j < 64; j += 2) {
            float4 va = *(float4*)(Vs + j * 64 + tx * 4);
            float4 vb = *(float4*)(Vs + (j + 1) * 64 + tx * 4);
            u64 v2[4] = {pack2(va.x, vb.x), pack2(va.y, vb.y),
                         pack2(va.z, vb.z), pack2(va.w, vb.w)};
#pragma unroll
            for (int i = 0; i < 8; i++) {
                u64 p2 = *(u64*)(Ps + (ty * 8 + i) * PS_STRIDE + j);
#pragma unroll
                for (int u = 0; u < 4; u++)
                    o2[i][u] = ffma2(p2, v2[u], o2[i][u]);
            }
        }
    }

    // Epilogue: sum packed halves, normalize, store O as [B*S, H*C]
#pragma unroll
    for (int i = 0; i < 8; i++) {
        float inv = 1.0f / lrow[i];
        float r[4];
#pragma unroll
        for (int u = 0; u < 4; u++) {
            float lo, hi;
            unpack2(lo, hi, o2[i][u]);
            r[u] = (lo + hi) * inv;
        }
        int row = qt * 128 + ty * 8 + i;
        *(float4*)(O + (size_t)(b * S_ + row) * N_ + h * C_ + tx * 4) =
            make_float4(r[0], r[1], r[2], r[3]);
    }
}

// ---------------------------------------------------------------------------
extern "C" void kernel_launch(void* const* d_in, const int* in_sizes, int n_in,
                              void* d_out, int out_size) {
    const float* x  = (const float*)d_in[0];
    const float* Wq = (const float*)d_in[1];
    const float* Wk = (const float*)d_in[2];
    const float* Wv = (const float*)d_in[3];
    const float* Wo = (const float*)d_in[4];
    float* out = (float*)d_out;

    float *q, *k, *v, *o;
    cudaGetSymbolAddress((void**)&q, g_q);
    cudaGetSymbolAddress((void**)&k, g_k);
    cudaGetSymbolAddress((void**)&v, g_v);
    cudaGetSymbolAddress((void**)&o, g_o);

    cudaFuncSetAttribute(attn_kernel,
                         cudaFuncAttributeMaxDynamicSharedMemorySize,
                         ATTN_SMEM_BYTES);

    dim3 gg(N_ / 128, M_ / 128);   // (8, 32)
    dim3 tt(256);

    sgemm_kernel<<<gg, tt>>>(x, Wq, q, QSCALE);
    sgemm_kernel<<<gg, tt>>>(x, Wk, k, 1.0f);
    sgemm_kernel<<<gg, tt>>>(x, Wv, v, 1.0f);

    dim3 ga(S_ / 128, H_, B_);     // (16, 16, 2)
    attn_kernel<<<ga, 256, ATTN_SMEM_BYTES>>>(q, k, v, o);

    sgemm_kernel<<<gg, tt>>>(o, Wo, out, 1.0f);
}